// round 10
// baseline (speedup 1.0000x reference)
#include <cuda_runtime.h>

#define NN   2048
#define MEM  1024
#define NCTA 128
#define TPB  256

typedef unsigned long long ull;

// Persistent device scratch (allocation-free rule: __device__ globals).
__device__ __align__(16) float g_h[MEM];            // recurrent hidden broadcast
__device__ __align__(16) float g_v[MEM];            // z*tanh(c) broadcast
__device__ __align__(128) unsigned g_bar;           // arrival counter (self-resetting)

__device__ __forceinline__ float sigf(float x) { return 1.0f / (1.0f + expf(-x)); }

__device__ __forceinline__ float warpSum(float v) {
#pragma unroll
    for (int o = 16; o > 0; o >>= 1) v += __shfl_down_sync(0xffffffffu, v, o);
    return v;
}

__device__ __forceinline__ void fma2(ull& acc, ull a, ull b) {
    asm("fma.rn.f32x2 %0, %1, %2, %0;" : "+l"(acc) : "l"(a), "l"(b));
}
__device__ __forceinline__ float2 unpk(ull p) {
    float2 r; asm("mov.b64 {%0,%1}, %2;" : "=f"(r.x), "=f"(r.y) : "l"(p)); return r;
}
__device__ __forceinline__ ull pk(float a, float b) {
    ull p; asm("mov.b64 %0, {%1,%2};" : "=l"(p) : "f"(a), "f"(b)); return p;
}
__device__ __forceinline__ unsigned ld_acquire_u32(const unsigned* p) {
    unsigned v;
    asm volatile("ld.acquire.gpu.global.u32 %0, [%1];" : "=r"(v) : "l"(p));
    return v;
}
__device__ __forceinline__ void red_release_add(unsigned* p, unsigned v) {
    asm volatile("red.release.gpu.global.add.u32 [%0], %1;" :: "l"(p), "r"(v)
                 : "memory");
}
__device__ __forceinline__ void stcg_f4(float* p, float4 v) {
    asm volatile("st.global.cg.v4.f32 [%0], {%1,%2,%3,%4};"
                 :: "l"(p), "f"(v.x), "f"(v.y), "f"(v.z), "f"(v.w) : "memory");
}

// Dynamic smem layout (floats)
#define SM_WXS   0                     // 40*1024 : CTA's 40 Wx columns, [c][k]
#define SM_XBUF  (40 * MEM)            // 1024    : broadcast h / v
#define SM_XROW  (41 * MEM)            // 1024    : staged inputs row
#define SM_SSH   (42 * MEM)            // 16      : per-warp publish staging (pad)
#define SM_RING  (42 * MEM + 16)       // 2*40    : Gx ring [slot][w*5+g]
#define SM_FLOATS (42 * MEM + 16 + 80)
#define SMEM_BYTES (SM_FLOATS * 4)

// ---------------------------------------------------------------------------
// Fused kernel: per-step Gx projection hidden inside the scan's barrier
// waits. 128 CTAs x 8 warps; warp w of CTA b owns state dim m = 8b + w:
//  - 4 Wh gate columns + 1 Wum column in registers (packed f32x2)
//  - 5 Wx gate columns (i,o,f,z,u) in SMEM; node t+2's Gx slice is computed
//    after the v-publish of step t (shadow of the v-barrier) into a 2-slot
//    smem ring consumed at step t+2.
// Sync topology: round-3-proven. Per phase, thread 0 alone stores the CTA's
// 8 floats (st.cg) + ONE red.release (same-thread ordering), and thread 0
// alone polls the single counter with ld.acquire. All 128 CTAs co-resident.
// CTA 0 drains the counter to 256*NN at the end and rearms it to 0 so the
// kernel is graph-replay safe without a helper launch.
// ---------------------------------------------------------------------------
__global__ void __launch_bounds__(TPB, 1) fused_scan_kernel(
    const float* __restrict__ inputs, const float* __restrict__ Wx,
    const float* __restrict__ bx,
    const float* __restrict__ Wh,  const float* __restrict__ bh,
    const float* __restrict__ Wum, const float* __restrict__ bum,
    const float* __restrict__ pic, const float* __restrict__ pfc,
    const float* __restrict__ poc, const float* __restrict__ pzc,
    float* __restrict__ out)
{
    extern __shared__ float sm[];
    float* wxs  = sm + SM_WXS;
    float* xbuf = sm + SM_XBUF;
    float* xrow = sm + SM_XROW;
    float* ssh  = sm + SM_SSH;
    float* ring = sm + SM_RING;

    const int tid  = threadIdx.x;
    const int w    = tid >> 5;
    const int lane = tid & 31;
    const int m0   = blockIdx.x * 8;
    const int m    = m0 + w;                    // this warp's state dim

    // ---- stage this CTA's 40 Wx columns into smem (one-time) ----
#pragma unroll 1
    for (int c = 0; c < 40; ++c) {
        const int col = (c % 5) * MEM + m0 + (c / 5);  // c = wd*5+g -> col(g,wd)
        for (int k = tid; k < MEM; k += TPB)
            wxs[c * MEM + k] = __ldg(&Wx[(size_t)k * (5 * MEM) + col]);
    }
    // note: c = wd*5 + g maps to wxs row index; warp w uses rows w*5+g.

    // ---- load + pack recurrent weights into registers (once) ----
    ulonglong2 wrp[8][4];   // Wh columns {g*MEM+m}, packed pairs over k
    ulonglong2 wmp[8];      // Wum column m
#pragma unroll
    for (int i = 0; i < 8; ++i) {
        const int k = (i * 32 + lane) * 4;
#pragma unroll
        for (int g = 0; g < 4; ++g) {
            const int col = g * MEM + m;
            const float a = __ldg(&Wh[(size_t)(k + 0) * (4 * MEM) + col]);
            const float b = __ldg(&Wh[(size_t)(k + 1) * (4 * MEM) + col]);
            const float c = __ldg(&Wh[(size_t)(k + 2) * (4 * MEM) + col]);
            const float d = __ldg(&Wh[(size_t)(k + 3) * (4 * MEM) + col]);
            wrp[i][g].x = pk(a, b);
            wrp[i][g].y = pk(c, d);
        }
        const float a = __ldg(&Wum[(size_t)(k + 0) * MEM + m]);
        const float b = __ldg(&Wum[(size_t)(k + 1) * MEM + m]);
        const float c = __ldg(&Wum[(size_t)(k + 2) * MEM + m]);
        const float d = __ldg(&Wum[(size_t)(k + 3) * MEM + m]);
        wmp[i].x = pk(a, b);
        wmp[i].y = pk(c, d);
    }

    // per-dim constants (lane 0 of each warp)
    float bh_i = 0, bh_o = 0, bh_f = 0, bh_z = 0, bum_v = 0;
    float pic_v = 0, pfc_v = 0, poc_v = 0, pzc_v = 0;
    float bxr[5] = {0, 0, 0, 0, 0};
    if (lane == 0) {
        bh_i = bh[m];           bh_o = bh[MEM + m];
        bh_f = bh[2 * MEM + m]; bh_z = bh[3 * MEM + m];
        bum_v = bum[m];
        pic_v = pic[m]; pfc_v = pfc[m]; poc_v = poc[m]; pzc_v = pzc[m];
#pragma unroll
        for (int g = 0; g < 5; ++g) bxr[g] = __ldg(&bx[g * MEM + m]);
    }
    float cp = 0.0f, hmx = -3.402823466e38f;

    float4* xbuf4 = (float4*)xbuf;

    // ---- GEMM produce: Gx slice for node tn into ring slot ----
    // (macro-ish lambda to keep syncs explicit at each call site)
    auto produce = [&](int tn, int slot) {
        __syncthreads();   // prior xrow readers done / wxs ready (first call)
        ((float4*)xrow)[tid] =
            __ldg((const float4*)(inputs + (size_t)tn * MEM) + tid);
        __syncthreads();   // xrow staged
        const ulonglong2* x2 = (const ulonglong2*)xrow;
#pragma unroll
        for (int g = 0; g < 5; ++g) {
            const ulonglong2* w2 = (const ulonglong2*)(wxs + (w * 5 + g) * MEM);
            ull a0 = 0ull, a1 = 0ull;
#pragma unroll
            for (int j = 0; j < 8; ++j) {
                const ulonglong2 xv = x2[j * 32 + lane];
                const ulonglong2 wv = w2[j * 32 + lane];
                fma2(a0, xv.x, wv.x);
                fma2(a1, xv.y, wv.y);
            }
            const float2 p = unpk(a0), q = unpk(a1);
            const float s = warpSum(p.x + p.y + q.x + q.y);
            if (lane == 0) ring[slot * 40 + w * 5 + g] = s + bxr[g];
        }
    };

    // ---- prologue: produce nodes 0 and 1 ----
    produce(0, 0);
    produce(1, 1);
    __syncthreads();       // ring[0..1] visible to all warps

#pragma unroll 1
    for (unsigned t = 0; t < NN; ++t) {
        // gx for node t from the smem ring (written at step t-2 / prologue)
        float gxi = 0, gxo = 0, gxf = 0, gxz = 0, gxu = 0;
        if (lane == 0) {
            const float* r = ring + (t & 1) * 40 + w * 5;
            gxi = r[0]; gxo = r[1]; gxf = r[2]; gxz = r[3]; gxu = r[4];
        }

        // ---- acquire h(t-1) ----
        if (t == 0) {
            xbuf4[tid] = make_float4(0.f, 0.f, 0.f, 0.f);
        } else {
            if (tid == 0) while (ld_acquire_u32(&g_bar) < 256u * t) { }
            __syncthreads();
            xbuf4[tid] = __ldcg(((const float4*)g_h) + tid);
        }
        __syncthreads();

        // ---- phase 1: 4 gate-column dots + gates, publish v ----
        ull acc[4][2] = {{0ull, 0ull}, {0ull, 0ull}, {0ull, 0ull}, {0ull, 0ull}};
        const ulonglong2* hp2 = (const ulonglong2*)xbuf;
#pragma unroll
        for (int i = 0; i < 8; ++i) {
            const ulonglong2 hp = hp2[i * 32 + lane];
#pragma unroll
            for (int g = 0; g < 4; ++g) {
                fma2(acc[g][0], hp.x, wrp[i][g].x);
                fma2(acc[g][1], hp.y, wrp[i][g].y);
            }
        }
        float2 e0 = unpk(acc[0][0]), o0 = unpk(acc[0][1]);
        float2 e1 = unpk(acc[1][0]), o1 = unpk(acc[1][1]);
        float2 e2 = unpk(acc[2][0]), o2 = unpk(acc[2][1]);
        float2 e3 = unpk(acc[3][0]), o3 = unpk(acc[3][1]);
        const float s0 = warpSum(e0.x + e0.y + o0.x + o0.y);
        const float s1 = warpSum(e1.x + e1.y + o1.x + o1.y);
        const float s2 = warpSum(e2.x + e2.y + o2.x + o2.y);
        const float s3 = warpSum(e3.x + e3.y + o3.x + o3.y);

        float iv = 0.f, fv = 0.f, opre = 0.f;
        if (lane == 0) {
            iv   = sigf(gxi + s0 + bh_i + pic_v * cp);
            fv   = sigf(gxf + s2 + bh_f + pfc_v * cp);
            const float zv = sigf(gxz + s3 + bh_z + pzc_v * cp);
            opre = gxo + s1 + bh_o;
            ssh[w] = zv * tanhf(cp);
        }
        __syncthreads();
        if (tid == 0) {
            stcg_f4(&g_v[m0],     *(float4*)&ssh[0]);
            stcg_f4(&g_v[m0 + 4], *(float4*)&ssh[4]);
            red_release_add(&g_bar, 1u);   // same-thread release orders stores
        }

        // ---- hidden work: Gx for node t+2 (shadow of the v-barrier) ----
        if (t + 2 < NN) produce((int)t + 2, (int)(t & 1));

        // ---- v-barrier detect + acquire v(t) ----
        if (tid == 0) while (ld_acquire_u32(&g_bar) < 256u * t + 128u) { }
        __syncthreads();
        xbuf4[tid] = __ldcg(((const float4*)g_v) + tid);
        __syncthreads();

        // ---- phase 2: Wum dot, u/c/o/h, publish h ----
        ull b0 = 0ull, b1 = 0ull;
        const ulonglong2* vp2 = (const ulonglong2*)xbuf;
#pragma unroll
        for (int i = 0; i < 8; ++i) {
            const ulonglong2 vp = vp2[i * 32 + lane];
            fma2(b0, vp.x, wmp[i].x);
            fma2(b1, vp.y, wmp[i].y);
        }
        float2 be = unpk(b0), bo = unpk(b1);
        const float sb = warpSum(be.x + be.y + bo.x + bo.y);

        if (lane == 0) {
            const float u  = tanhf(gxu + sb + bum_v);
            const float c  = iv * u + fv * cp;
            const float oo = sigf(opre + poc_v * c);
            const float hh = oo * tanhf(c);
            cp  = c;
            hmx = fmaxf(hmx, hh);
            ssh[w] = hh;
        }
        __syncthreads();
        if (tid == 0) {
            stcg_f4(&g_h[m0],     *(float4*)&ssh[0]);
            stcg_f4(&g_h[m0 + 4], *(float4*)&ssh[4]);
            red_release_add(&g_bar, 1u);
        }
        // next iteration's h-acquire performs the poll for 256*(t+1)
    }

    if (lane == 0) out[m] = hmx;

    // ---- rearm the counter for the next graph replay ----
    if (blockIdx.x == 0 && tid == 0) {
        while (ld_acquire_u32(&g_bar) < 256u * NN) { }   // all arrivals landed
        asm volatile("st.global.cg.u32 [%0], %1;"
                     :: "l"(&g_bar), "r"(0u) : "memory");
    }
}

// ---------------------------------------------------------------------------
extern "C" void kernel_launch(void* const* d_in, const int* in_sizes, int n_in,
                              void* d_out, int out_size) {
    const float* inputs = (const float*)d_in[0];
    const float* Wx     = (const float*)d_in[1];
    const float* bx     = (const float*)d_in[2];
    const float* Wh     = (const float*)d_in[3];
    const float* bh     = (const float*)d_in[4];
    const float* Wum    = (const float*)d_in[5];
    const float* bum    = (const float*)d_in[6];
    const float* pic    = (const float*)d_in[7];
    const float* pfc    = (const float*)d_in[8];
    const float* poc    = (const float*)d_in[9];
    const float* pzc    = (const float*)d_in[10];
    float* out = (float*)d_out;

    cudaFuncSetAttribute(fused_scan_kernel,
                         cudaFuncAttributeMaxDynamicSharedMemorySize,
                         SMEM_BYTES);
    fused_scan_kernel<<<NCTA, TPB, SMEM_BYTES>>>(
        inputs, Wx, bx, Wh, bh, Wum, bum, pic, pfc, poc, pzc, out);
}

// round 11
// speedup vs baseline: 1.2861x; 1.2861x over previous
#include <cuda_runtime.h>

#define NN   2048
#define MEM  1024
#define NCTA 128
#define TPB  256

typedef unsigned long long ull;

// Persistent device scratch (allocation-free rule: __device__ globals).
__device__ __align__(16) float g_Gx[NN * 5 * MEM];  // 40 MB input projection
__device__ __align__(16) float g_h[MEM];            // recurrent hidden broadcast
__device__ __align__(16) float g_v[MEM];            // z*tanh(c) broadcast
__device__ __align__(128) unsigned g_bar;           // single arrival counter

__device__ __forceinline__ float sigf(float x) { return 1.0f / (1.0f + expf(-x)); }

__device__ __forceinline__ float warpSum(float v) {
#pragma unroll
    for (int o = 16; o > 0; o >>= 1) v += __shfl_down_sync(0xffffffffu, v, o);
    return v;
}

__device__ __forceinline__ void fma2(ull& acc, ull a, ull b) {
    asm("fma.rn.f32x2 %0, %1, %2, %0;" : "+l"(acc) : "l"(a), "l"(b));
}
__device__ __forceinline__ float2 unpk(ull p) {
    float2 r; asm("mov.b64 {%0,%1}, %2;" : "=f"(r.x), "=f"(r.y) : "l"(p)); return r;
}
__device__ __forceinline__ ull pk(float a, float b) {
    ull p; asm("mov.b64 %0, {%1,%2};" : "=l"(p) : "f"(a), "f"(b)); return p;
}
__device__ __forceinline__ unsigned ld_acquire_u32(const unsigned* p) {
    unsigned v;
    asm volatile("ld.acquire.gpu.global.u32 %0, [%1];" : "=r"(v) : "l"(p));
    return v;
}
__device__ __forceinline__ void red_release_add(unsigned* p, unsigned v) {
    asm volatile("red.release.gpu.global.add.u32 [%0], %1;" :: "l"(p), "r"(v)
                 : "memory");
}
__device__ __forceinline__ void stcg_f32(float* p, float v) {
    asm volatile("st.global.cg.f32 [%0], %1;" :: "l"(p), "f"(v) : "memory");
}

// ---------------------------------------------------------------------------
// Kernel 1: Gx = inputs @ Wx + bx   (2048 x 1024) @ (1024 x 5120)
// Classic 128x128x8 SGEMM (~120us total, issue-bound — near-free vs the scan).
// Block (0,0) also resets the scan arrival counter for this graph replay.
// ---------------------------------------------------------------------------
__global__ void __launch_bounds__(256) gemm_gx_kernel(
    const float* __restrict__ A,   // inputs (2048,1024)
    const float* __restrict__ B,   // Wx (1024,5120)
    const float* __restrict__ bx)  // (5120,)
{
    if (blockIdx.x == 0 && blockIdx.y == 0 && threadIdx.x == 0) g_bar = 0u;

    __shared__ float As[8][128];
    __shared__ float Bs[8][132];

    const int tid  = threadIdx.x;
    const int tx   = tid & 15;
    const int ty   = tid >> 4;
    const int arow = tid >> 1;
    const int akc  = (tid & 1) << 2;
    const int bkr  = tid >> 5;
    const int bcol = (tid & 31) << 2;

    const int m0 = blockIdx.y << 7;
    const int n0 = blockIdx.x << 7;

    const float* Aptr = A + (m0 + arow) * 1024 + akc;
    const float* Bptr = B + bkr * 5120 + n0 + bcol;

    float acc[8][8];
#pragma unroll
    for (int i = 0; i < 8; ++i)
#pragma unroll
        for (int j = 0; j < 8; ++j) acc[i][j] = 0.0f;

    for (int kt = 0; kt < 1024; kt += 8) {
        const float4 av = __ldg((const float4*)(Aptr + kt));
        const float4 bv = __ldg((const float4*)(Bptr + kt * 5120));
        As[akc + 0][arow] = av.x;
        As[akc + 1][arow] = av.y;
        As[akc + 2][arow] = av.z;
        As[akc + 3][arow] = av.w;
        *(float4*)&Bs[bkr][bcol] = bv;
        __syncthreads();

#pragma unroll
        for (int k = 0; k < 8; ++k) {
            float ar[8], br[8];
            *(float4*)(ar)     = *(const float4*)&As[k][ty * 8];
            *(float4*)(ar + 4) = *(const float4*)&As[k][ty * 8 + 4];
            *(float4*)(br)     = *(const float4*)&Bs[k][tx * 8];
            *(float4*)(br + 4) = *(const float4*)&Bs[k][tx * 8 + 4];
#pragma unroll
            for (int i = 0; i < 8; ++i)
#pragma unroll
                for (int j = 0; j < 8; ++j) acc[i][j] += ar[i] * br[j];
        }
        __syncthreads();
    }

    const int crow = m0 + ty * 8;
    const int ccol = n0 + tx * 8;
    float bxv[8];
    *(float4*)(bxv)     = __ldg((const float4*)&bx[ccol]);
    *(float4*)(bxv + 4) = __ldg((const float4*)&bx[ccol + 4]);
#pragma unroll
    for (int i = 0; i < 8; ++i) {
        float4 c0 = make_float4(acc[i][0] + bxv[0], acc[i][1] + bxv[1],
                                acc[i][2] + bxv[2], acc[i][3] + bxv[3]);
        float4 c1 = make_float4(acc[i][4] + bxv[4], acc[i][5] + bxv[5],
                                acc[i][6] + bxv[6], acc[i][7] + bxv[7]);
        *(float4*)&g_Gx[(size_t)(crow + i) * 5120 + ccol]     = c0;
        *(float4*)&g_Gx[(size_t)(crow + i) * 5120 + ccol + 4] = c1;
    }
}

// ---------------------------------------------------------------------------
// Kernel 2: persistent scan. 128 CTAs x 8 warps; warp w of CTA b owns state
// dim m = 8b + w (4 Wh gate columns + 1 Wum column in registers, packed
// f32x2). Critical-path-ordered step:
//   phase 1: z-column dot FIRST -> publish v immediately (per-warp direct
//   st.cg, bar, one red.release by tid0 — store->bar->release transitive hb);
//   the i/f/o dots + gates run in the v-barrier SHADOW (they feed phase 2
//   only). phase 2: Wum dot -> u,c,o,h -> publish h the same way.
// Detect: thread 0 alone polls the single counter with ld.acquire (proven
// topology). All 128 CTAs co-resident (<=148 SMs at 1 CTA/SM).
// ---------------------------------------------------------------------------
__global__ void __launch_bounds__(TPB, 1) scan_kernel(
    const float* __restrict__ Wh,  const float* __restrict__ bh,
    const float* __restrict__ Wum, const float* __restrict__ bum,
    const float* __restrict__ pic, const float* __restrict__ pfc,
    const float* __restrict__ poc, const float* __restrict__ pzc,
    float* __restrict__ out)
{
    __shared__ __align__(16) float xbuf[MEM];   // broadcast h (ph1) / v (ph2)

    const int tid  = threadIdx.x;
    const int w    = tid >> 5;
    const int lane = tid & 31;
    const int m    = blockIdx.x * 8 + w;        // this warp's state dim

    // ---- load + pack recurrent weights into registers (once) ----
    ulonglong2 wrp[8][4];   // Wh columns {g*MEM+m}, packed pairs over k
    ulonglong2 wmp[8];      // Wum column m
#pragma unroll
    for (int i = 0; i < 8; ++i) {
        const int k = (i * 32 + lane) * 4;
#pragma unroll
        for (int g = 0; g < 4; ++g) {
            const int col = g * MEM + m;
            const float a = __ldg(&Wh[(size_t)(k + 0) * (4 * MEM) + col]);
            const float b = __ldg(&Wh[(size_t)(k + 1) * (4 * MEM) + col]);
            const float c = __ldg(&Wh[(size_t)(k + 2) * (4 * MEM) + col]);
            const float d = __ldg(&Wh[(size_t)(k + 3) * (4 * MEM) + col]);
            wrp[i][g].x = pk(a, b);
            wrp[i][g].y = pk(c, d);
        }
        const float a = __ldg(&Wum[(size_t)(k + 0) * MEM + m]);
        const float b = __ldg(&Wum[(size_t)(k + 1) * MEM + m]);
        const float c = __ldg(&Wum[(size_t)(k + 2) * MEM + m]);
        const float d = __ldg(&Wum[(size_t)(k + 3) * MEM + m]);
        wmp[i].x = pk(a, b);
        wmp[i].y = pk(c, d);
    }

    // per-dim constants (lane 0 of each warp)
    float bh_i = 0, bh_o = 0, bh_f = 0, bh_z = 0, bum_v = 0;
    float pic_v = 0, pfc_v = 0, poc_v = 0, pzc_v = 0;
    if (lane == 0) {
        bh_i = bh[m];           bh_o = bh[MEM + m];
        bh_f = bh[2 * MEM + m]; bh_z = bh[3 * MEM + m];
        bum_v = bum[m];
        pic_v = pic[m]; pfc_v = pfc[m]; poc_v = poc[m]; pzc_v = pzc[m];
    }
    float cp = 0.0f, hmx = -3.402823466e38f;

    float4* xbuf4 = (float4*)xbuf;
    __syncthreads();

#pragma unroll 1
    for (unsigned t = 0; t < NN; ++t) {
        // Gx prefetch (independent of sync; hides under the h-poll)
        float gxi = 0, gxo = 0, gxf = 0, gxz = 0, gxu = 0;
        if (lane == 0) {
            const float* gx = g_Gx + (size_t)t * (5 * MEM) + m;
            gxi = __ldg(gx);
            gxo = __ldg(gx + MEM);
            gxf = __ldg(gx + 2 * MEM);
            gxz = __ldg(gx + 3 * MEM);
            gxu = __ldg(gx + 4 * MEM);
        }

        // ---- acquire h(t-1) ----
        if (t == 0) {
            xbuf4[tid] = make_float4(0.f, 0.f, 0.f, 0.f);
        } else {
            if (tid == 0) while (ld_acquire_u32(&g_bar) < 256u * t) { }
            __syncthreads();
            xbuf4[tid] = __ldcg(((const float4*)g_h) + tid);
        }
        __syncthreads();

        const ulonglong2* hp2 = (const ulonglong2*)xbuf;

        // ---- phase 1a: z-column dot ONLY -> publish v ASAP ----
        ull az0 = 0ull, az1 = 0ull;
#pragma unroll
        for (int i = 0; i < 8; ++i) {
            const ulonglong2 hp = hp2[i * 32 + lane];
            fma2(az0, hp.x, wrp[i][3].x);
            fma2(az1, hp.y, wrp[i][3].y);
        }
        const float2 ze = unpk(az0), zo = unpk(az1);
        const float s3 = warpSum(ze.x + ze.y + zo.x + zo.y);
        if (lane == 0) {
            const float zv = sigf(gxz + s3 + bh_z + pzc_v * cp);
            stcg_f32(&g_v[m], zv * tanhf(cp));   // per-warp direct publish
        }
        __syncthreads();                          // all 8 v-stores issued
        if (tid == 0) red_release_add(&g_bar, 1u);  // st -> bar -> release hb

        // ---- phase 1b (v-barrier shadow): i/o/f dots + gates for phase 2 ----
        ull acc[3][2] = {{0ull, 0ull}, {0ull, 0ull}, {0ull, 0ull}};
#pragma unroll
        for (int i = 0; i < 8; ++i) {
            const ulonglong2 hp = hp2[i * 32 + lane];
#pragma unroll
            for (int g = 0; g < 3; ++g) {
                fma2(acc[g][0], hp.x, wrp[i][g].x);
                fma2(acc[g][1], hp.y, wrp[i][g].y);
            }
        }
        const float2 e0 = unpk(acc[0][0]), o0 = unpk(acc[0][1]);
        const float2 e1 = unpk(acc[1][0]), o1 = unpk(acc[1][1]);
        const float2 e2 = unpk(acc[2][0]), o2 = unpk(acc[2][1]);
        const float s0 = warpSum(e0.x + e0.y + o0.x + o0.y);
        const float s1 = warpSum(e1.x + e1.y + o1.x + o1.y);
        const float s2 = warpSum(e2.x + e2.y + o2.x + o2.y);

        float iv = 0.f, fv = 0.f, opre = 0.f;
        if (lane == 0) {
            iv   = sigf(gxi + s0 + bh_i + pic_v * cp);
            fv   = sigf(gxf + s2 + bh_f + pfc_v * cp);
            opre = gxo + s1 + bh_o;
        }

        // ---- v-barrier detect + acquire v(t) ----
        if (tid == 0) while (ld_acquire_u32(&g_bar) < 256u * t + 128u) { }
        __syncthreads();
        xbuf4[tid] = __ldcg(((const float4*)g_v) + tid);
        __syncthreads();

        // ---- phase 2: Wum dot, u/c/o/h, publish h ----
        ull b0 = 0ull, b1 = 0ull;
        const ulonglong2* vp2 = (const ulonglong2*)xbuf;
#pragma unroll
        for (int i = 0; i < 8; ++i) {
            const ulonglong2 vp = vp2[i * 32 + lane];
            fma2(b0, vp.x, wmp[i].x);
            fma2(b1, vp.y, wmp[i].y);
        }
        const float2 be = unpk(b0), bo = unpk(b1);
        const float sb = warpSum(be.x + be.y + bo.x + bo.y);

        float hh = 0.f;
        if (lane == 0) {
            const float u  = tanhf(gxu + sb + bum_v);
            const float c  = iv * u + fv * cp;
            const float oo = sigf(opre + poc_v * c);
            hh = oo * tanhf(c);
            cp = c;
            stcg_f32(&g_h[m], hh);               // per-warp direct publish
        }
        __syncthreads();                          // all 8 h-stores issued
        if (tid == 0) red_release_add(&g_bar, 1u);
        if (lane == 0) hmx = fmaxf(hmx, hh);      // off the critical path
        // next iteration's h-acquire performs the poll for 256*(t+1)
    }

    if (lane == 0) out[m] = hmx;
}

// ---------------------------------------------------------------------------
extern "C" void kernel_launch(void* const* d_in, const int* in_sizes, int n_in,
                              void* d_out, int out_size) {
    const float* inputs = (const float*)d_in[0];
    const float* Wx     = (const float*)d_in[1];
    const float* bx     = (const float*)d_in[2];
    const float* Wh     = (const float*)d_in[3];
    const float* bh     = (const float*)d_in[4];
    const float* Wum    = (const float*)d_in[5];
    const float* bum    = (const float*)d_in[6];
    const float* pic    = (const float*)d_in[7];
    const float* pfc    = (const float*)d_in[8];
    const float* poc    = (const float*)d_in[9];
    const float* pzc    = (const float*)d_in[10];
    float* out = (float*)d_out;

    dim3 gg(5120 / 128, 2048 / 128);
    gemm_gx_kernel<<<gg, 256>>>(inputs, Wx, bx);
    scan_kernel<<<NCTA, TPB>>>(Wh, bh, Wum, bum,
                               pic, pfc, poc, pzc, out);
}

// round 12
// speedup vs baseline: 1.3784x; 1.0717x over previous
#include <cuda_runtime.h>

#define NN   2048
#define MEM  1024
#define NCTA 128
#define TPB  256

typedef unsigned long long ull;

// Persistent device scratch (allocation-free rule: __device__ globals).
__device__ __align__(16) float g_Gx[NN * 5 * MEM];  // 40 MB input projection
__device__ __align__(16) float g_h[MEM];            // recurrent hidden broadcast
__device__ __align__(16) float g_v[MEM];            // z*tanh(c) broadcast
__device__ __align__(128) unsigned g_bar;           // single arrival counter

__device__ __forceinline__ float tanhfast(float x) {
    float y; asm("tanh.approx.f32 %0, %1;" : "=f"(y) : "f"(x)); return y;
}
__device__ __forceinline__ float sigfast(float x) {
    return 0.5f * tanhfast(0.5f * x) + 0.5f;
}

__device__ __forceinline__ float warpSum(float v) {
#pragma unroll
    for (int o = 16; o > 0; o >>= 1) v += __shfl_down_sync(0xffffffffu, v, o);
    return v;
}

__device__ __forceinline__ void fma2(ull& acc, ull a, ull b) {
    asm("fma.rn.f32x2 %0, %1, %2, %0;" : "+l"(acc) : "l"(a), "l"(b));
}
__device__ __forceinline__ float2 unpk(ull p) {
    float2 r; asm("mov.b64 {%0,%1}, %2;" : "=f"(r.x), "=f"(r.y) : "l"(p)); return r;
}
__device__ __forceinline__ ull pk(float a, float b) {
    ull p; asm("mov.b64 %0, {%1,%2};" : "=l"(p) : "f"(a), "f"(b)); return p;
}
__device__ __forceinline__ unsigned ld_acquire_u32(const unsigned* p) {
    unsigned v;
    asm volatile("ld.acquire.gpu.global.u32 %0, [%1];" : "=r"(v) : "l"(p));
    return v;
}
__device__ __forceinline__ void red_release_add(unsigned* p, unsigned v) {
    asm volatile("red.release.gpu.global.add.u32 [%0], %1;" :: "l"(p), "r"(v)
                 : "memory");
}
__device__ __forceinline__ void stcg_f32(float* p, float v) {
    asm volatile("st.global.cg.f32 [%0], %1;" :: "l"(p), "f"(v) : "memory");
}

// 4-lane pipelined poll (warp 0 only): lanes 0..3 run independent dependent
// ld.acquire chains -> counter sampled ~4x per L2 round trip. 512 pollers on
// one line chip-wide (~1 read/cyc) — 4x the proven-safe density, 8x below
// the storm regime. The observing lane's acquire + the CTA barrier after
// this call give the transitive happens-before for the payload loads.
__device__ __forceinline__ void poll4(const unsigned* p, unsigned tgt) {
    const int lane = threadIdx.x & 31;
    for (;;) {
        unsigned v = 0;
        if (lane < 4) v = ld_acquire_u32(p);
        if (__any_sync(0xffffffffu, v >= tgt)) break;
    }
}

// ---------------------------------------------------------------------------
// Kernel 1: Gx = inputs @ Wx + bx   (2048 x 1024) @ (1024 x 5120)
// Classic 128x128x8 SGEMM (~120us total — near-free vs the scan).
// Block (0,0) also resets the scan arrival counter for this graph replay.
// ---------------------------------------------------------------------------
__global__ void __launch_bounds__(256) gemm_gx_kernel(
    const float* __restrict__ A,   // inputs (2048,1024)
    const float* __restrict__ B,   // Wx (1024,5120)
    const float* __restrict__ bx)  // (5120,)
{
    if (blockIdx.x == 0 && blockIdx.y == 0 && threadIdx.x == 0) g_bar = 0u;

    __shared__ float As[8][128];
    __shared__ float Bs[8][132];

    const int tid  = threadIdx.x;
    const int tx   = tid & 15;
    const int ty   = tid >> 4;
    const int arow = tid >> 1;
    const int akc  = (tid & 1) << 2;
    const int bkr  = tid >> 5;
    const int bcol = (tid & 31) << 2;

    const int m0 = blockIdx.y << 7;
    const int n0 = blockIdx.x << 7;

    const float* Aptr = A + (m0 + arow) * 1024 + akc;
    const float* Bptr = B + bkr * 5120 + n0 + bcol;

    float acc[8][8];
#pragma unroll
    for (int i = 0; i < 8; ++i)
#pragma unroll
        for (int j = 0; j < 8; ++j) acc[i][j] = 0.0f;

    for (int kt = 0; kt < 1024; kt += 8) {
        const float4 av = __ldg((const float4*)(Aptr + kt));
        const float4 bv = __ldg((const float4*)(Bptr + kt * 5120));
        As[akc + 0][arow] = av.x;
        As[akc + 1][arow] = av.y;
        As[akc + 2][arow] = av.z;
        As[akc + 3][arow] = av.w;
        *(float4*)&Bs[bkr][bcol] = bv;
        __syncthreads();

#pragma unroll
        for (int k = 0; k < 8; ++k) {
            float ar[8], br[8];
            *(float4*)(ar)     = *(const float4*)&As[k][ty * 8];
            *(float4*)(ar + 4) = *(const float4*)&As[k][ty * 8 + 4];
            *(float4*)(br)     = *(const float4*)&Bs[k][tx * 8];
            *(float4*)(br + 4) = *(const float4*)&Bs[k][tx * 8 + 4];
#pragma unroll
            for (int i = 0; i < 8; ++i)
#pragma unroll
                for (int j = 0; j < 8; ++j) acc[i][j] += ar[i] * br[j];
        }
        __syncthreads();
    }

    const int crow = m0 + ty * 8;
    const int ccol = n0 + tx * 8;
    float bxv[8];
    *(float4*)(bxv)     = __ldg((const float4*)&bx[ccol]);
    *(float4*)(bxv + 4) = __ldg((const float4*)&bx[ccol + 4]);
#pragma unroll
    for (int i = 0; i < 8; ++i) {
        float4 c0 = make_float4(acc[i][0] + bxv[0], acc[i][1] + bxv[1],
                                acc[i][2] + bxv[2], acc[i][3] + bxv[3]);
        float4 c1 = make_float4(acc[i][4] + bxv[4], acc[i][5] + bxv[5],
                                acc[i][6] + bxv[6], acc[i][7] + bxv[7]);
        *(float4*)&g_Gx[(size_t)(crow + i) * 5120 + ccol]     = c0;
        *(float4*)&g_Gx[(size_t)(crow + i) * 5120 + ccol + 4] = c1;
    }
}

// ---------------------------------------------------------------------------
// Kernel 2: persistent scan. 128 CTAs x 8 warps; warp w of CTA b owns state
// dim m = 8b + w (4 Wh gate columns + 1 Wum column in registers, packed
// f32x2). Critical-path-ordered step (round-11 topology):
//   phase 1: z-column dot FIRST -> publish v (per-warp st.cg, bar, one
//   red.release); i/o/f dots + gates run in the v-barrier SHADOW.
//   phase 2: Wum dot -> u,c,o,h (hw tanh.approx) -> publish h.
// Detect: 4-lane pipelined poll in warp 0. All 128 CTAs co-resident.
// ---------------------------------------------------------------------------
__global__ void __launch_bounds__(TPB, 1) scan_kernel(
    const float* __restrict__ Wh,  const float* __restrict__ bh,
    const float* __restrict__ Wum, const float* __restrict__ bum,
    const float* __restrict__ pic, const float* __restrict__ pfc,
    const float* __restrict__ poc, const float* __restrict__ pzc,
    float* __restrict__ out)
{
    __shared__ __align__(16) float xbuf[MEM];   // broadcast h (ph1) / v (ph2)

    const int tid  = threadIdx.x;
    const int w    = tid >> 5;
    const int lane = tid & 31;
    const int m    = blockIdx.x * 8 + w;        // this warp's state dim

    // ---- load + pack recurrent weights into registers (once) ----
    ulonglong2 wrp[8][4];   // Wh columns {g*MEM+m}, packed pairs over k
    ulonglong2 wmp[8];      // Wum column m
#pragma unroll
    for (int i = 0; i < 8; ++i) {
        const int k = (i * 32 + lane) * 4;
#pragma unroll
        for (int g = 0; g < 4; ++g) {
            const int col = g * MEM + m;
            const float a = __ldg(&Wh[(size_t)(k + 0) * (4 * MEM) + col]);
            const float b = __ldg(&Wh[(size_t)(k + 1) * (4 * MEM) + col]);
            const float c = __ldg(&Wh[(size_t)(k + 2) * (4 * MEM) + col]);
            const float d = __ldg(&Wh[(size_t)(k + 3) * (4 * MEM) + col]);
            wrp[i][g].x = pk(a, b);
            wrp[i][g].y = pk(c, d);
        }
        const float a = __ldg(&Wum[(size_t)(k + 0) * MEM + m]);
        const float b = __ldg(&Wum[(size_t)(k + 1) * MEM + m]);
        const float c = __ldg(&Wum[(size_t)(k + 2) * MEM + m]);
        const float d = __ldg(&Wum[(size_t)(k + 3) * MEM + m]);
        wmp[i].x = pk(a, b);
        wmp[i].y = pk(c, d);
    }

    // per-dim constants (lane 0 of each warp)
    float bh_i = 0, bh_o = 0, bh_f = 0, bh_z = 0, bum_v = 0;
    float pic_v = 0, pfc_v = 0, poc_v = 0, pzc_v = 0;
    if (lane == 0) {
        bh_i = bh[m];           bh_o = bh[MEM + m];
        bh_f = bh[2 * MEM + m]; bh_z = bh[3 * MEM + m];
        bum_v = bum[m];
        pic_v = pic[m]; pfc_v = pfc[m]; poc_v = poc[m]; pzc_v = pzc[m];
    }
    float cp = 0.0f, hmx = -3.402823466e38f;

    float4* xbuf4 = (float4*)xbuf;
    __syncthreads();

#pragma unroll 1
    for (unsigned t = 0; t < NN; ++t) {
        // Gx prefetch (independent of sync; hides under the h-poll)
        float gxi = 0, gxo = 0, gxf = 0, gxz = 0, gxu = 0;
        if (lane == 0) {
            const float* gx = g_Gx + (size_t)t * (5 * MEM) + m;
            gxi = __ldg(gx);
            gxo = __ldg(gx + MEM);
            gxf = __ldg(gx + 2 * MEM);
            gxz = __ldg(gx + 3 * MEM);
            gxu = __ldg(gx + 4 * MEM);
        }

        // ---- acquire h(t-1) ----
        if (t == 0) {
            xbuf4[tid] = make_float4(0.f, 0.f, 0.f, 0.f);
        } else {
            if (w == 0) poll4(&g_bar, 256u * t);
            __syncthreads();
            xbuf4[tid] = __ldcg(((const float4*)g_h) + tid);
        }
        __syncthreads();

        const ulonglong2* hp2 = (const ulonglong2*)xbuf;

        // ---- phase 1a: z-column dot ONLY -> publish v ASAP ----
        ull az0 = 0ull, az1 = 0ull;
#pragma unroll
        for (int i = 0; i < 8; ++i) {
            const ulonglong2 hp = hp2[i * 32 + lane];
            fma2(az0, hp.x, wrp[i][3].x);
            fma2(az1, hp.y, wrp[i][3].y);
        }
        const float2 ze = unpk(az0), zo = unpk(az1);
        const float s3 = warpSum(ze.x + ze.y + zo.x + zo.y);
        if (lane == 0) {
            const float zv = sigfast(gxz + s3 + bh_z + pzc_v * cp);
            stcg_f32(&g_v[m], zv * tanhfast(cp));   // per-warp direct publish
        }
        __syncthreads();                          // all 8 v-stores issued
        if (tid == 0) red_release_add(&g_bar, 1u);  // st -> bar -> release hb

        // ---- phase 1b (v-barrier shadow): i/o/f dots + gates for phase 2 ----
        ull acc[3][2] = {{0ull, 0ull}, {0ull, 0ull}, {0ull, 0ull}};
#pragma unroll
        for (int i = 0; i < 8; ++i) {
            const ulonglong2 hp = hp2[i * 32 + lane];
#pragma unroll
            for (int g = 0; g < 3; ++g) {
                fma2(acc[g][0], hp.x, wrp[i][g].x);
                fma2(acc[g][1], hp.y, wrp[i][g].y);
            }
        }
        const float2 e0 = unpk(acc[0][0]), o0 = unpk(acc[0][1]);
        const float2 e1 = unpk(acc[1][0]), o1 = unpk(acc[1][1]);
        const float2 e2 = unpk(acc[2][0]), o2 = unpk(acc[2][1]);
        const float s0 = warpSum(e0.x + e0.y + o0.x + o0.y);
        const float s1 = warpSum(e1.x + e1.y + o1.x + o1.y);
        const float s2 = warpSum(e2.x + e2.y + o2.x + o2.y);

        float iv = 0.f, fv = 0.f, opre = 0.f;
        if (lane == 0) {
            iv   = sigfast(gxi + s0 + bh_i + pic_v * cp);
            fv   = sigfast(gxf + s2 + bh_f + pfc_v * cp);
            opre = gxo + s1 + bh_o;
        }

        // ---- v-barrier detect + acquire v(t) ----
        if (w == 0) poll4(&g_bar, 256u * t + 128u);
        __syncthreads();
        xbuf4[tid] = __ldcg(((const float4*)g_v) + tid);
        __syncthreads();

        // ---- phase 2: Wum dot, u/c/o/h, publish h ----
        ull b0 = 0ull, b1 = 0ull;
        const ulonglong2* vp2 = (const ulonglong2*)xbuf;
#pragma unroll
        for (int i = 0; i < 8; ++i) {
            const ulonglong2 vp = vp2[i * 32 + lane];
            fma2(b0, vp.x, wmp[i].x);
            fma2(b1, vp.y, wmp[i].y);
        }
        const float2 be = unpk(b0), bo = unpk(b1);
        const float sb = warpSum(be.x + be.y + bo.x + bo.y);

        float hh = 0.f;
        if (lane == 0) {
            const float u  = tanhfast(gxu + sb + bum_v);
            const float c  = iv * u + fv * cp;
            const float oo = sigfast(opre + poc_v * c);
            hh = oo * tanhfast(c);
            cp = c;
            stcg_f32(&g_h[m], hh);               // per-warp direct publish
        }
        __syncthreads();                          // all 8 h-stores issued
        if (tid == 0) red_release_add(&g_bar, 1u);
        if (lane == 0) hmx = fmaxf(hmx, hh);      // off the critical path
        // next iteration's h-acquire performs the poll for 256*(t+1)
    }

    if (lane == 0) out[m] = hmx;
}

// ---------------------------------------------------------------------------
extern "C" void kernel_launch(void* const* d_in, const int* in_sizes, int n_in,
                              void* d_out, int out_size) {
    const float* inputs = (const float*)d_in[0];
    const float* Wx     = (const float*)d_in[1];
    const float* bx     = (const float*)d_in[2];
    const float* Wh     = (const float*)d_in[3];
    const float* bh     = (const float*)d_in[4];
    const float* Wum    = (const float*)d_in[5];
    const float* bum    = (const float*)d_in[6];
    const float* pic    = (const float*)d_in[7];
    const float* pfc    = (const float*)d_in[8];
    const float* poc    = (const float*)d_in[9];
    const float* pzc    = (const float*)d_in[10];
    float* out = (float*)d_out;

    dim3 gg(5120 / 128, 2048 / 128);
    gemm_gx_kernel<<<gg, 256>>>(inputs, Wx, bx);
    scan_kernel<<<NCTA, TPB>>>(Wh, bh, Wum, bum,
                               pic, pfc, poc, pzc, out);
}